// round 10
// baseline (speedup 1.0000x reference)
#include <cuda_runtime.h>
#include <math.h>

typedef unsigned long long ull;
#define FULLMASK 0xFFFFFFFFu

static const int NMAX = 8192;
static const int KSEL = 16;

// Static device scratch (no allocation allowed).
__device__ float2 g_ch2m[NMAX];
__device__ int    g_idx[NMAX * KSEL];
__device__ float  g_part[64];

// ---------------------------------------------------------------------------
// Kernel A: ch2m[a] = polynomial(ch2[a]; M1, M2)
// y = M[0][0] + M[0][1]*x2 + M[1][0]*x1 + M[1][1]*x1*x2
// ---------------------------------------------------------------------------
__global__ void poly_kernel(const float* __restrict__ ch2,
                            const float* __restrict__ M1,
                            const float* __restrict__ M2,
                            int N)
{
    int i = blockIdx.x * blockDim.x + threadIdx.x;
    if (i >= N) return;
    float x1 = ch2[2 * i];
    float x2 = ch2[2 * i + 1];
    float a00 = __ldg(M1 + 0), a01 = __ldg(M1 + 1), a10 = __ldg(M1 + 2), a11 = __ldg(M1 + 3);
    float b00 = __ldg(M2 + 0), b01 = __ldg(M2 + 1), b10 = __ldg(M2 + 2), b11 = __ldg(M2 + 3);
    float x12 = __fmul_rn(x1, x2);
    float y1 = __fadd_rn(__fadd_rn(a00, __fmul_rn(a01, x2)),
                         __fadd_rn(__fmul_rn(a10, x1), __fmul_rn(a11, x12)));
    float y2 = __fadd_rn(__fadd_rn(b00, __fmul_rn(b01, x2)),
                         __fadd_rn(__fmul_rn(b10, x1), __fmul_rn(b11, x12)));
    g_ch2m[i] = make_float2(y1, y2);
}

// ---------------------------------------------------------------------------
// Kernel B: exact 16-NN per query, warp-per-query.
// Top-16 kept as warp-distributed sorted list: lane l holds rank l (l<16) as
// packed u64 (dist_bits<<32 | index)  -> u64 ascending == (dist asc, idx asc),
// matching jax.lax.top_k tie-breaking exactly.
// ---------------------------------------------------------------------------
__device__ __forceinline__ float sqdist_rn(float px, float py, float qx, float qy)
{
    float dx = __fadd_rn(px, -qx);
    float dy = __fadd_rn(py, -qy);
    // Deliberately no FMA contraction: matches reference (diff*diff then sum).
    return __fadd_rn(__fmul_rn(dx, dx), __fmul_rn(dy, dy));
}

__global__ void __launch_bounds__(256) knn_kernel(const float* __restrict__ ch1, int N)
{
    const int lane = threadIdx.x & 31;
    const int warp = threadIdx.x >> 5;
    const int q = blockIdx.x * 8 + warp;
    if (q >= N) return;

    const float qx = __ldg(ch1 + 2 * q);
    const float qy = __ldg(ch1 + 2 * q + 1);
    const float2* __restrict__ pts = g_ch2m;

    // --- Prefill: candidates 0..31, bitonic-sort ascending across the warp ---
    {
        float2 p = __ldg(&pts[lane]);
        float d = sqdist_rn(p.x, p.y, qx, qy);
        ull e = ((ull)__float_as_uint(d) << 32) | (unsigned)lane;
        #pragma unroll
        for (int k = 2; k <= 32; k <<= 1) {
            #pragma unroll
            for (int j = k >> 1; j >= 1; j >>= 1) {
                ull o = __shfl_xor_sync(FULLMASK, e, j);
                bool dir = ((lane & k) == 0);           // ascending segment
                bool takeMin = (((lane & j) == 0) == dir);
                ull mn = (e < o) ? e : o;
                ull mx = (e < o) ? o : e;
                e = takeMin ? mn : mx;
            }
        }
        // main scan state lives in 'e'; continue below
        ull wpk = __shfl_sync(FULLMASK, e, 15);              // current 16th (packed)
        float wd = __uint_as_float((unsigned)(wpk >> 32));   // its distance

        // --- Main scan: candidates 32..N-1, 32 per iteration ---
        for (int base = 32; base < N; base += 32) {
            float2 pc = __ldg(&pts[base + lane]);
            float d = sqdist_rn(pc.x, pc.y, qx, qy);
            unsigned m = __ballot_sync(FULLMASK, d <= wd);
            if (m) {
                // rare path: serialize candidate insertions (uniform control)
                do {
                    int s = __ffs(m) - 1;
                    m &= m - 1;
                    float vd = __shfl_sync(FULLMASK, d, s);
                    ull pv = ((ull)__float_as_uint(vd) << 32) | (unsigned)(base + s);
                    if (pv < wpk) {   // strictly better than current 16th (lex)
                        ull up = __shfl_up_sync(FULLMASK, e, 1);
                        unsigned lm = __ballot_sync(FULLMASK, pv < e);
                        int pos = __ffs(lm) - 1;  // lm != 0 since lane 15 qualifies
                        if (lane == pos)      e = pv;
                        else if (lane > pos)  e = up;
                        wpk = __shfl_sync(FULLMASK, e, 15);
                    }
                } while (m);
                wd = __uint_as_float((unsigned)(wpk >> 32));
            }
        }

        if (lane < KSEL) g_idx[q * KSEL + lane] = (int)(e & 0xFFFFFFFFull);
    }
}

// ---------------------------------------------------------------------------
// Kernel C: scrambled gather + exp/log reduction.
// expD[q] = (1/N) * sum_{p<16} exp( -sqdist(ch2m[idx[q/16 + (N/16)*p][q%16]], ch1[q]) / 4.5 )
// term[q] = -log(expD[q])   (expD is provably nonzero for this data range)
// ---------------------------------------------------------------------------
__global__ void __launch_bounds__(256) reduce_kernel(const float* __restrict__ ch1,
                                                     int N, int NK)
{
    int q = blockIdx.x * blockDim.x + threadIdx.x;
    float term = 0.0f;
    if (q < N) {
        float qx = ch1[2 * q];
        float qy = ch1[2 * q + 1];
        int s  = q % KSEL;
        int r0 = q / KSEL;
        float acc = 0.0f;
        #pragma unroll
        for (int p = 0; p < KSEL; ++p) {
            int a = g_idx[(r0 + p * NK) * KSEL + s];
            float2 pa = g_ch2m[a];
            float d = sqdist_rn(pa.x, pa.y, qx, qy);
            acc += expf(d * (-1.0f / 4.5f));
        }
        float expD = acc / (float)N;
        if (expD != 0.0f) term = -logf(expD);
    }
    __shared__ float red[256];
    red[threadIdx.x] = term;
    __syncthreads();
    #pragma unroll
    for (int off = 128; off > 0; off >>= 1) {
        if (threadIdx.x < off) red[threadIdx.x] += red[threadIdx.x + off];
        __syncthreads();
    }
    if (threadIdx.x == 0) g_part[blockIdx.x] = red[0];
}

__global__ void final_kernel(float* __restrict__ out, int npart)
{
    float v = 0.0f;
    for (int i = threadIdx.x; i < npart; i += 32) v += g_part[i];
    #pragma unroll
    for (int off = 16; off > 0; off >>= 1) v += __shfl_down_sync(FULLMASK, v, off);
    if (threadIdx.x == 0) out[0] = v;
}

// ---------------------------------------------------------------------------
extern "C" void kernel_launch(void* const* d_in, const int* in_sizes, int n_in,
                              void* d_out, int out_size)
{
    const float* ch1 = (const float*)d_in[0];
    const float* ch2 = (const float*)d_in[1];
    const float* M1  = (const float*)d_in[2];
    const float* M2  = (const float*)d_in[3];
    int N = in_sizes[0] / 2;   // 8192

    poly_kernel<<<(N + 255) / 256, 256>>>(ch2, M1, M2, N);

    int nb = (N + 7) / 8;      // one warp per query, 8 warps/block
    knn_kernel<<<nb, 256>>>(ch1, N);

    int nc = (N + 255) / 256;  // 32 blocks
    reduce_kernel<<<nc, 256>>>(ch1, N, N / KSEL);

    final_kernel<<<1, 32>>>((float*)d_out, nc);
}

// round 11
// speedup vs baseline: 1.1608x; 1.1608x over previous
#include <cuda_runtime.h>
#include <math.h>

typedef unsigned long long ull;
#define FULLMASK 0xFFFFFFFFu

static const int NMAX = 8192;
static const int KSEL = 16;

// Static device scratch (no allocation allowed).
__device__ float2 g_ch2m[NMAX];
__device__ int    g_idx[NMAX * KSEL];

// ---------------------------------------------------------------------------
// Kernel A: ch2m[a] = polynomial(ch2[a]; M1, M2); also zero-init the output
// accumulator (d_out is poisoned to 0xAA before each timed replay).
// y = M[0][0] + M[0][1]*x2 + M[1][0]*x1 + M[1][1]*x1*x2
// ---------------------------------------------------------------------------
__global__ void poly_kernel(const float* __restrict__ ch2,
                            const float* __restrict__ M1,
                            const float* __restrict__ M2,
                            float* __restrict__ out,
                            int N)
{
    int i = blockIdx.x * blockDim.x + threadIdx.x;
    if (i == 0) out[0] = 0.0f;
    if (i >= N) return;
    float x1 = ch2[2 * i];
    float x2 = ch2[2 * i + 1];
    float a00 = __ldg(M1 + 0), a01 = __ldg(M1 + 1), a10 = __ldg(M1 + 2), a11 = __ldg(M1 + 3);
    float b00 = __ldg(M2 + 0), b01 = __ldg(M2 + 1), b10 = __ldg(M2 + 2), b11 = __ldg(M2 + 3);
    float x12 = __fmul_rn(x1, x2);
    float y1 = __fadd_rn(__fadd_rn(a00, __fmul_rn(a01, x2)),
                         __fadd_rn(__fmul_rn(a10, x1), __fmul_rn(a11, x12)));
    float y2 = __fadd_rn(__fadd_rn(b00, __fmul_rn(b01, x2)),
                         __fadd_rn(__fmul_rn(b10, x1), __fmul_rn(b11, x12)));
    g_ch2m[i] = make_float2(y1, y2);
}

// ---------------------------------------------------------------------------
// Kernel B: exact 16-NN per query, warp-per-query.
// Top-16 kept as warp-distributed sorted list: lane l holds rank l (l<16) as
// packed u64 (dist_bits<<32 | index) -> u64 ascending == (dist asc, idx asc),
// matching jax.lax.top_k tie-breaking exactly. Insertion order within a batch
// cannot change the final set (exact set maintenance), so candidates are
// consumed 2-per-lane from float4 loads.
// ---------------------------------------------------------------------------
__device__ __forceinline__ float sqd(float px, float py, float qx, float qy)
{
    float dx = __fadd_rn(px, -qx);
    float dy = __fadd_rn(py, -qy);
    return __fmaf_rn(dy, dy, __fmul_rn(dx, dx));
}

__device__ __forceinline__ void insert16(ull& e, ull& wpk, ull pv, int lane)
{
    if (pv < wpk) {                       // strictly better than current 16th (lex)
        ull up = __shfl_up_sync(FULLMASK, e, 1);
        unsigned lm = __ballot_sync(FULLMASK, pv < e);
        int pos = __ffs(lm) - 1;          // lm != 0 since lane 15 qualifies
        if (lane == pos)      e = pv;
        else if (lane > pos)  e = up;
        wpk = __shfl_sync(FULLMASK, e, 15);
    }
}

// Drain a ballot mask of passing candidates; cand index = base2 + 2*s + off.
__device__ __forceinline__ void drain16(unsigned m, float d, int base2, int off,
                                        ull& e, ull& wpk, int lane)
{
    while (m) {
        int s = __ffs(m) - 1;
        m &= m - 1;
        float vd = __shfl_sync(FULLMASK, d, s);
        ull pv = ((ull)__float_as_uint(vd) << 32) | (unsigned)(base2 + 2 * s + off);
        insert16(e, wpk, pv, lane);
    }
}

__global__ void __launch_bounds__(256) knn_kernel(const float* __restrict__ ch1, int N)
{
    const int lane = threadIdx.x & 31;
    const int warp = threadIdx.x >> 5;
    const int q = blockIdx.x * 8 + warp;
    if (q >= N) return;

    const float qx = __ldg(ch1 + 2 * q);
    const float qy = __ldg(ch1 + 2 * q + 1);
    const float2* __restrict__ pts = g_ch2m;
    const float4* __restrict__ p4  = (const float4*)g_ch2m;

    // --- Prefill: candidates 0..31, bitonic-sort ascending across the warp ---
    float2 p = __ldg(&pts[lane]);
    float dp = sqd(p.x, p.y, qx, qy);
    ull e = ((ull)__float_as_uint(dp) << 32) | (unsigned)lane;
    #pragma unroll
    for (int k = 2; k <= 32; k <<= 1) {
        #pragma unroll
        for (int j = k >> 1; j >= 1; j >>= 1) {
            ull o = __shfl_xor_sync(FULLMASK, e, j);
            bool dir = ((lane & k) == 0);           // ascending segment
            bool takeMin = (((lane & j) == 0) == dir);
            ull mn = (e < o) ? e : o;
            ull mx = (e < o) ? o : e;
            e = takeMin ? mn : mx;
        }
    }
    ull wpk = __shfl_sync(FULLMASK, e, 15);              // current 16th (packed)
    float wd = __uint_as_float((unsigned)(wpk >> 32));   // its distance

    // --- Main scan: 64 candidates per iteration (2 per lane via float4) ---
    for (int b4 = 16; b4 < N / 2; b4 += 32) {            // float4 index base (cand 32..N-1)
        float4 c = __ldg(p4 + b4 + lane);
        float d0 = sqd(c.x, c.y, qx, qy);
        float d1 = sqd(c.z, c.w, qx, qy);
        if (__any_sync(FULLMASK, (d0 <= wd) | (d1 <= wd))) {
            unsigned m0 = __ballot_sync(FULLMASK, d0 <= wd);
            unsigned m1 = __ballot_sync(FULLMASK, d1 <= wd);
            int base2 = 2 * b4;
            drain16(m0, d0, base2, 0, e, wpk, lane);
            drain16(m1, d1, base2, 1, e, wpk, lane);
            wd = __uint_as_float((unsigned)(wpk >> 32));
        }
    }

    if (lane < KSEL) g_idx[q * KSEL + lane] = (int)(e & 0xFFFFFFFFull);
}

// ---------------------------------------------------------------------------
// Kernel C: scrambled gather + exp/log reduction, block partial -> atomicAdd.
// expD[q] = (1/N) * sum_{p<16} exp( -sqdist(ch2m[idx[q/16 + (N/16)*p][q%16]], ch1[q]) / 4.5 )
// out = -sum_q log(expD[q])   (expD is provably nonzero for this data range)
// ---------------------------------------------------------------------------
__global__ void __launch_bounds__(256) reduce_kernel(const float* __restrict__ ch1,
                                                     float* __restrict__ out,
                                                     int N, int NK)
{
    int q = blockIdx.x * blockDim.x + threadIdx.x;
    float term = 0.0f;
    if (q < N) {
        float qx = ch1[2 * q];
        float qy = ch1[2 * q + 1];
        int s  = q % KSEL;
        int r0 = q / KSEL;
        float acc = 0.0f;
        #pragma unroll
        for (int pp = 0; pp < KSEL; ++pp) {
            int a = __ldg(&g_idx[(r0 + pp * NK) * KSEL + s]);
            float2 pa = g_ch2m[a];
            float d = sqd(pa.x, pa.y, qx, qy);
            acc += __expf(d * (-1.0f / 4.5f));
        }
        float expD = acc / (float)N;
        if (expD != 0.0f) term = -__logf(expD);
    }
    __shared__ float red[256];
    red[threadIdx.x] = term;
    __syncthreads();
    #pragma unroll
    for (int off = 128; off > 0; off >>= 1) {
        if (threadIdx.x < off) red[threadIdx.x] += red[threadIdx.x + off];
        __syncthreads();
    }
    if (threadIdx.x == 0) atomicAdd(out, red[0]);
}

// ---------------------------------------------------------------------------
extern "C" void kernel_launch(void* const* d_in, const int* in_sizes, int n_in,
                              void* d_out, int out_size)
{
    const float* ch1 = (const float*)d_in[0];
    const float* ch2 = (const float*)d_in[1];
    const float* M1  = (const float*)d_in[2];
    const float* M2  = (const float*)d_in[3];
    float* out = (float*)d_out;
    int N = in_sizes[0] / 2;   // 8192

    poly_kernel<<<(N + 255) / 256, 256>>>(ch2, M1, M2, out, N);

    int nb = (N + 7) / 8;      // one warp per query, 8 warps/block
    knn_kernel<<<nb, 256>>>(ch1, N);

    int nc = (N + 255) / 256;  // 32 blocks
    reduce_kernel<<<nc, 256>>>(ch1, out, N, N / KSEL);
}